// round 1
// baseline (speedup 1.0000x reference)
#include <cuda_runtime.h>
#include <math.h>

#define B_   32
#define NF_  128
#define FLAT_ 784
#define HID2_ 392
#define EO_  64
#define FIN_ 8192
#define FHID_ 4096
#define OUT_ 53

// ---------------- scratch (static device allocations) ----------------
__device__ float g_a1[32 * 32 * 112 * 112];   // conv1 out (pooled)
__device__ float g_a2[32 * 64 * 56 * 56];     // conv2 out
__device__ float g_f [32 * 128 * 28 * 28];    // conv3 out == f [B][NF][784]
__device__ float g_lg[32 * 128];              // attention logits
__device__ float g_at[32 * 128];              // attention softmax
__device__ float g_h1[32 * 128 * 784];
__device__ float g_h2[32 * 128 * 392];
__device__ float g_e [32 * 8192];
__device__ float g_g1[32 * 8192];
__device__ float g_g2[32 * 4096];

// ---------------- fused conv3x3(SAME) + bias + relu + maxpool2 ----------------
template<int CI, int CO_T>
__global__ __launch_bounds__(256)
void conv_pool_kernel(const float* __restrict__ in, const float* __restrict__ w,
                      const float* __restrict__ bias, float* __restrict__ out,
                      int H, int W, int CO)
{
    __shared__ float sw[CO_T * CI * 9];
    const int tid = threadIdx.x;
    const int co0 = blockIdx.y * CO_T;
    const int b   = blockIdx.z;

    // weights for this co-group are contiguous in [CO][CI][3][3]
    for (int i = tid; i < CO_T * CI * 9; i += blockDim.x)
        sw[i] = w[(long)co0 * CI * 9 + i];
    __syncthreads();

    const int HP = H >> 1, WP = W >> 1;
    const int p = blockIdx.x * blockDim.x + tid;
    if (p >= HP * WP) return;
    const int py = p / WP, px = p % WP;
    const int y0 = 2 * py, x0 = 2 * px;

    float acc[CO_T][4];
#pragma unroll
    for (int t = 0; t < CO_T; t++) {
        acc[t][0] = acc[t][1] = acc[t][2] = acc[t][3] = 0.f;
    }

    for (int ci = 0; ci < CI; ci++) {
        const float* ip = in + ((long)(b * CI + ci)) * H * W;
        float v[4][4];
#pragma unroll
        for (int r = 0; r < 4; r++) {
            const int yy = y0 - 1 + r;
            const bool yok = (yy >= 0) && (yy < H);
#pragma unroll
            for (int c = 0; c < 4; c++) {
                const int xx = x0 - 1 + c;
                const bool ok = yok && (xx >= 0) && (xx < W);
                v[r][c] = ok ? __ldg(ip + (long)yy * W + xx) : 0.f;
            }
        }
        const float* swc = sw + ci * 9;
#pragma unroll
        for (int t = 0; t < CO_T; t++) {
            const float* wt = swc + t * CI * 9;
#pragma unroll
            for (int ky = 0; ky < 3; ky++) {
#pragma unroll
                for (int kx = 0; kx < 3; kx++) {
                    const float wv = wt[ky * 3 + kx];
                    acc[t][0] = fmaf(v[ky    ][kx    ], wv, acc[t][0]);
                    acc[t][1] = fmaf(v[ky    ][kx + 1], wv, acc[t][1]);
                    acc[t][2] = fmaf(v[ky + 1][kx    ], wv, acc[t][2]);
                    acc[t][3] = fmaf(v[ky + 1][kx + 1], wv, acc[t][3]);
                }
            }
        }
    }
#pragma unroll
    for (int t = 0; t < CO_T; t++) {
        const float bv = bias[co0 + t];
        float m = fmaxf(fmaxf(acc[t][0], acc[t][1]), fmaxf(acc[t][2], acc[t][3])) + bv;
        m = fmaxf(m, 0.f);
        out[(((long)b * CO + co0 + t) * HP + py) * WP + px] = m;
    }
}

// ---------------- attention ----------------
__global__ void attn_logits_kernel(const float* __restrict__ f, const float* __restrict__ wa,
                                   const float* __restrict__ ba, float* __restrict__ logits)
{
    const int n = blockIdx.x, b = blockIdx.y;
    const float* fp = f + ((long)b * NF_ + n) * FLAT_;
    float s = 0.f;
    for (int k = threadIdx.x; k < FLAT_; k += 128)
        s += fp[k] * wa[k];
    __shared__ float red[128];
    red[threadIdx.x] = s;
    __syncthreads();
    for (int off = 64; off > 0; off >>= 1) {
        if (threadIdx.x < off) red[threadIdx.x] += red[threadIdx.x + off];
        __syncthreads();
    }
    if (threadIdx.x == 0) logits[b * NF_ + n] = red[0] + ba[0];
}

__global__ void attn_softmax_kernel(const float* __restrict__ logits, float* __restrict__ att)
{
    __shared__ float sh[128];
    const int b = blockIdx.x, n = threadIdx.x;
    const float v = logits[b * NF_ + n];
    sh[n] = v;
    __syncthreads();
    for (int off = 64; off > 0; off >>= 1) {
        if (n < off) sh[n] = fmaxf(sh[n], sh[n + off]);
        __syncthreads();
    }
    const float mx = sh[0];
    __syncthreads();
    const float e = expf(v - mx);
    sh[n] = e;
    __syncthreads();
    for (int off = 64; off > 0; off >>= 1) {
        if (n < off) sh[n] += sh[n + off];
        __syncthreads();
    }
    att[b * NF_ + n] = e / sh[0];
}

// ---------------- init output with bias (for atomic-accumulate GEMMs) ----------------
__global__ void init_bias_kernel(float* __restrict__ C, const float* __restrict__ bias, int N, int M)
{
    const int i = blockIdx.x * blockDim.x + threadIdx.x;
    if (i < M * N) C[i] = bias[i % N];
}

// ---------------- skinny batched GEMM: C[32,N] = op(A[32,K]) @ W[K,N] ----------------
// 128 threads: 4 b-groups (8 rows each) x 32 j-threads (4 cols each). K tiled by 32.
template<bool ARELU, bool ASCALE, bool ATOMIC, bool ORELU>
__global__ __launch_bounds__(128)
void gemm_m32_kernel(const float* __restrict__ A, long strideA_n, long lda,
                     const float* __restrict__ scale,           // att base; s(b)=scale[b*128+n]
                     const float* __restrict__ W, long strideW_n,
                     const float* __restrict__ bias, long strideBias_n,
                     float* __restrict__ C, long strideC_n, long ldc,
                     int K, int N)
{
    const int n   = blockIdx.y;
    const int j0  = blockIdx.x * 128;
    const int tid = threadIdx.x;
    const int jt  = tid & 31;
    const int bg  = tid >> 5;

    A += (long)n * strideA_n;
    W += (long)n * strideW_n;
    C += (long)n * strideC_n;

    const int kchunks = (K + 31) >> 5;
    const int per = (kchunks + gridDim.z - 1) / gridDim.z;
    const int c0 = blockIdx.z * per;
    const int c1 = min(kchunks, c0 + per);

    __shared__ float Ast[32][36];    // [k][b], padded so rows stay 16B aligned
    __shared__ float Ws[32][128];
    __shared__ float ssc[32];

    if (ASCALE) {
        if (tid < 32) ssc[tid] = scale[(long)tid * NF_ + n];
    }

    float acc[8][4];
#pragma unroll
    for (int r = 0; r < 8; r++)
#pragma unroll
        for (int c = 0; c < 4; c++) acc[r][c] = 0.f;

    for (int cc = c0; cc < c1; cc++) {
        const int k0 = cc << 5;
        __syncthreads();
        // A tile -> Ast[k][b]
#pragma unroll
        for (int i = 0; i < 8; i++) {
            const int b  = (tid >> 5) + i * 4;
            const int k  = tid & 31;
            const int kk = k0 + k;
            float v = (kk < K) ? __ldg(A + (long)b * lda + kk) : 0.f;
            if (ARELU)  v = fmaxf(v, 0.f);
            if (ASCALE) v *= ssc[b];
            Ast[k][b] = v;
        }
        // W tile -> Ws[k][j]
#pragma unroll
        for (int i = 0; i < 32; i++) {
            const int kk = k0 + i;
            const int jj = j0 + tid;
            Ws[i][tid] = (kk < K && jj < N) ? __ldg(W + (long)kk * N + jj) : 0.f;
        }
        __syncthreads();
#pragma unroll
        for (int k = 0; k < 32; k++) {
            const float4 w4 = *(const float4*)&Ws[k][jt * 4];
            float a[8];
            *(float4*)&a[0] = *(const float4*)&Ast[k][bg * 8];
            *(float4*)&a[4] = *(const float4*)&Ast[k][bg * 8 + 4];
#pragma unroll
            for (int r = 0; r < 8; r++) {
                acc[r][0] = fmaf(a[r], w4.x, acc[r][0]);
                acc[r][1] = fmaf(a[r], w4.y, acc[r][1]);
                acc[r][2] = fmaf(a[r], w4.z, acc[r][2]);
                acc[r][3] = fmaf(a[r], w4.w, acc[r][3]);
            }
        }
    }

    if (ATOMIC) {
#pragma unroll
        for (int r = 0; r < 8; r++) {
            const int b = bg * 8 + r;
#pragma unroll
            for (int c = 0; c < 4; c++) {
                const int j = j0 + jt * 4 + c;
                if (j < N) atomicAdd(&C[(long)b * ldc + j], acc[r][c]);
            }
        }
    } else {
        const float* bn = bias + (long)n * strideBias_n;
#pragma unroll
        for (int r = 0; r < 8; r++) {
            const int b = bg * 8 + r;
#pragma unroll
            for (int c = 0; c < 4; c++) {
                const int j = j0 + jt * 4 + c;
                if (j < N) {
                    float v = acc[r][c] + bn[j];
                    if (ORELU) v = fmaxf(v, 0.f);
                    C[(long)b * ldc + j] = v;
                }
            }
        }
    }
}

// ---------------- launch ----------------
extern "C" void kernel_launch(void* const* d_in, const int* in_sizes, int n_in,
                              void* d_out, int out_size)
{
    const float* x   = (const float*)d_in[0];
    const float* cw1 = (const float*)d_in[1];
    const float* cb1 = (const float*)d_in[2];
    const float* cw2 = (const float*)d_in[3];
    const float* cb2 = (const float*)d_in[4];
    const float* cw3 = (const float*)d_in[5];
    const float* cb3 = (const float*)d_in[6];
    const float* wa  = (const float*)d_in[7];
    const float* ba  = (const float*)d_in[8];
    const float* ew1 = (const float*)d_in[9];
    const float* eb1 = (const float*)d_in[10];
    const float* ew2 = (const float*)d_in[11];
    const float* eb2 = (const float*)d_in[12];
    const float* ew3 = (const float*)d_in[13];
    const float* eb3 = (const float*)d_in[14];
    const float* fw1 = (const float*)d_in[15];
    const float* fb1 = (const float*)d_in[16];
    const float* fw2 = (const float*)d_in[17];
    const float* fb2 = (const float*)d_in[18];
    const float* fw3 = (const float*)d_in[19];
    const float* fb3 = (const float*)d_in[20];
    float* out = (float*)d_out;

    float *a1, *a2, *f, *lg, *att, *h1, *h2, *e, *g1, *g2;
    cudaGetSymbolAddress((void**)&a1,  g_a1);
    cudaGetSymbolAddress((void**)&a2,  g_a2);
    cudaGetSymbolAddress((void**)&f,   g_f);
    cudaGetSymbolAddress((void**)&lg,  g_lg);
    cudaGetSymbolAddress((void**)&att, g_at);
    cudaGetSymbolAddress((void**)&h1,  g_h1);
    cudaGetSymbolAddress((void**)&h2,  g_h2);
    cudaGetSymbolAddress((void**)&e,   g_e);
    cudaGetSymbolAddress((void**)&g1,  g_g1);
    cudaGetSymbolAddress((void**)&g2,  g_g2);

    // CNN stem
    conv_pool_kernel<3, 8><<<dim3(49, 4, 32), 256>>>(x,  cw1, cb1, a1, 224, 224, 32);
    conv_pool_kernel<32, 8><<<dim3(13, 8, 32), 256>>>(a1, cw2, cb2, a2, 112, 112, 64);
    conv_pool_kernel<64, 8><<<dim3(4, 16, 32), 256>>>(a2, cw3, cb3, f,  56,  56,  128);

    // attention over feature maps
    attn_logits_kernel<<<dim3(128, 32), 128>>>(f, wa, ba, lg);
    attn_softmax_kernel<<<32, 128>>>(lg, att);

    // experts (att-scale fused into E1 A-load; bias+relu fused into stores)
    gemm_m32_kernel<false, true, false, true><<<dim3(7, 128, 1), 128>>>(
        f, 784L, 128L * 784, att, ew1, 784L * 784, eb1, 784L, h1, 784L, 128L * 784, 784, 784);
    gemm_m32_kernel<false, false, false, true><<<dim3(4, 128, 1), 128>>>(
        h1, 784L, 128L * 784, nullptr, ew2, 784L * 392, eb2, 392L, h2, 392L, 128L * 392, 784, 392);
    gemm_m32_kernel<false, false, false, true><<<dim3(1, 128, 1), 128>>>(
        h2, 392L, 128L * 392, nullptr, ew3, 392L * 64, eb3, 64L, e, 64L, 8192L, 392, 64);

    // head: K-split atomics, bias pre-init, relu deferred to consumer A-load
    init_bias_kernel<<<1024, 256>>>(g1, fb1, FIN_, B_);
    gemm_m32_kernel<false, false, true, false><<<dim3(64, 1, 8), 128>>>(
        e, 0L, 8192L, nullptr, fw1, 0L, nullptr, 0L, g1, 0L, 8192L, 8192, 8192);

    init_bias_kernel<<<512, 256>>>(g2, fb2, FHID_, B_);
    gemm_m32_kernel<true, false, true, false><<<dim3(32, 1, 8), 128>>>(
        g1, 0L, 8192L, nullptr, fw2, 0L, nullptr, 0L, g2, 0L, 4096L, 8192, 4096);

    init_bias_kernel<<<7, 256>>>(out, fb3, OUT_, B_);
    gemm_m32_kernel<true, false, true, false><<<dim3(1, 1, 16), 128>>>(
        g2, 0L, 4096L, nullptr, fw3, 0L, nullptr, 0L, out, 0L, 53L, 4096, 53);
}